// round 1
// baseline (speedup 1.0000x reference)
#include <cuda_runtime.h>
#include <math.h>

#define B_   16
#define N_   1024
#define D_   1024
#define H_   8
#define HD_  128
#define SCALE_ 0.08838834764831845f   /* 1/sqrt(128) */
#define NEG_   (-1.0e30f)

// -------- scratch (device globals; allocation is forbidden) --------
__device__ float g_q[(size_t)B_ * H_ * N_ * HD_];
__device__ float g_k[(size_t)B_ * H_ * N_ * HD_];
__device__ float g_v[(size_t)B_ * H_ * N_ * HD_];
__device__ float g_att[(size_t)B_ * N_ * D_];

// ============================================================================
// Kernel 1: fused QKV projection.
// For each (b,h): q/k/v[n,e] = x_b[n,:] @ W*_h[:,e] + b*.  64x64 output tile,
// BK=16, 256 threads, 4x4 microtile per thread, x tile shared by all 3 GEMMs.
// ============================================================================
__global__ __launch_bounds__(256) void qkv_kernel(
    const float* __restrict__ x,
    const float* __restrict__ Wq, const float* __restrict__ bq,
    const float* __restrict__ Wk, const float* __restrict__ bk,
    const float* __restrict__ Wv, const float* __restrict__ bv)
{
    __shared__ float As[16][64];
    __shared__ float Bqs[16][64];
    __shared__ float Bks[16][64];
    __shared__ float Bvs[16][64];

    const int bh = blockIdx.z;
    const int b  = bh >> 3;
    const int h  = bh & 7;
    const int rowBase = blockIdx.y * 64;
    const int colBase = blockIdx.x * 64;

    const float* A  = x  + (size_t)b * N_ * D_;
    const float* WQ = Wq + (size_t)h * D_ * HD_;
    const float* WK = Wk + (size_t)h * D_ * HD_;
    const float* WV = Wv + (size_t)h * D_ * HD_;

    const int tid = threadIdx.x;
    const int tx = tid & 15, ty = tid >> 4;

    float cq[4][4] = {}, ck[4][4] = {}, cv[4][4] = {};

    const int ar  = tid >> 2;        // 0..63 : A row
    const int ak  = (tid & 3) * 4;   // 0,4,8,12 : A k-offset (float4)
    const int wc  = tid & 63;        // weight col
    const int wk0 = tid >> 6;        // 0..3

    for (int k0 = 0; k0 < D_; k0 += 16) {
        float4 av = *(const float4*)(A + (size_t)(rowBase + ar) * D_ + k0 + ak);
        As[ak + 0][ar] = av.x;
        As[ak + 1][ar] = av.y;
        As[ak + 2][ar] = av.z;
        As[ak + 3][ar] = av.w;
        #pragma unroll
        for (int i = 0; i < 4; i++) {
            int kk = wk0 + i * 4;
            size_t gofs = (size_t)(k0 + kk) * HD_ + colBase + wc;
            Bqs[kk][wc] = WQ[gofs];
            Bks[kk][wc] = WK[gofs];
            Bvs[kk][wc] = WV[gofs];
        }
        __syncthreads();
        #pragma unroll
        for (int kk = 0; kk < 16; kk++) {
            float4 a4 = *(const float4*)&As[kk][ty * 4];
            float4 q4 = *(const float4*)&Bqs[kk][tx * 4];
            float4 k4 = *(const float4*)&Bks[kk][tx * 4];
            float4 v4 = *(const float4*)&Bvs[kk][tx * 4];
            float a[4]  = {a4.x, a4.y, a4.z, a4.w};
            float qv[4] = {q4.x, q4.y, q4.z, q4.w};
            float kv[4] = {k4.x, k4.y, k4.z, k4.w};
            float vv[4] = {v4.x, v4.y, v4.z, v4.w};
            #pragma unroll
            for (int i = 0; i < 4; i++) {
                #pragma unroll
                for (int j = 0; j < 4; j++) {
                    cq[i][j] += a[i] * qv[j];
                    ck[i][j] += a[i] * kv[j];
                    cv[i][j] += a[i] * vv[j];
                }
            }
        }
        __syncthreads();
    }

    #pragma unroll
    for (int i = 0; i < 4; i++) {
        int row = rowBase + ty * 4 + i;
        size_t base = ((size_t)bh * N_ + row) * HD_ + colBase + tx * 4;
        #pragma unroll
        for (int j = 0; j < 4; j++) {
            int col = colBase + tx * 4 + j;
            g_q[base + j] = cq[i][j] + bq[h * HD_ + col];
            g_k[base + j] = ck[i][j] + bk[h * HD_ + col];
            g_v[base + j] = cv[i][j] + bv[h * HD_ + col];
        }
    }
}

// ============================================================================
// Kernel 2: flash-style attention with online softmax + padding mask.
// One block = (b,h, 64-query tile). Loops over 64-key chunks.
// Mask: score kept only if qmask&&kmask else -1e30 (matches reference,
// including uniform softmax for fully-masked rows).
// Output written concatenated into g_att[b][n][h*128+e].
// ============================================================================
struct AttnSmem {
    float Qs[128][65];   // [e][row]
    float Ks[128][65];   // [e][key]
    float Vs[64][128];   // [key][e]
    float Ps[64][65];    // probs
    float row_max[64];
    float row_sum[64];
    float alpha[64];
    int   qm[64];
    int   km[64];
};

__global__ __launch_bounds__(256) void attn_kernel(const int* __restrict__ mask)
{
    extern __shared__ char smem_raw[];
    AttnSmem& s = *reinterpret_cast<AttnSmem*>(smem_raw);

    const int bh = blockIdx.y;
    const int b  = bh >> 3;
    const int h  = bh & 7;
    const int rowBase = blockIdx.x * 64;

    const int tid = threadIdx.x;
    const int tx = tid & 15, ty = tid >> 4;

    const float* Qg = g_q + ((size_t)bh * N_ + rowBase) * HD_;
    const float* Kg = g_k + (size_t)bh * N_ * HD_;
    const float* Vg = g_v + (size_t)bh * N_ * HD_;

    // load Q tile transposed
    {
        const int f  = tid & 31;   // float4 index in row
        const int r0 = tid >> 5;   // 0..7
        #pragma unroll
        for (int i = 0; i < 8; i++) {
            int r = r0 + i * 8;
            float4 v = *(const float4*)(Qg + (size_t)r * HD_ + f * 4);
            s.Qs[f * 4 + 0][r] = v.x;
            s.Qs[f * 4 + 1][r] = v.y;
            s.Qs[f * 4 + 2][r] = v.z;
            s.Qs[f * 4 + 3][r] = v.w;
        }
    }
    if (tid < 64) {
        s.row_max[tid] = -3.0e38f;
        s.row_sum[tid] = 0.0f;
        s.qm[tid] = mask[b * N_ + rowBase + tid];
    }

    float o[4][8];
    #pragma unroll
    for (int i = 0; i < 4; i++)
        #pragma unroll
        for (int j = 0; j < 8; j++) o[i][j] = 0.0f;

    for (int kb = 0; kb < N_; kb += 64) {
        __syncthreads();   // protect Ks/Vs/km reuse
        {
            const int f  = tid & 31;
            const int r0 = tid >> 5;
            #pragma unroll
            for (int i = 0; i < 8; i++) {
                int r = r0 + i * 8;
                float4 kv = *(const float4*)(Kg + (size_t)(kb + r) * HD_ + f * 4);
                s.Ks[f * 4 + 0][r] = kv.x;
                s.Ks[f * 4 + 1][r] = kv.y;
                s.Ks[f * 4 + 2][r] = kv.z;
                s.Ks[f * 4 + 3][r] = kv.w;
                float4 vv = *(const float4*)(Vg + (size_t)(kb + r) * HD_ + f * 4);
                *(float4*)&s.Vs[r][f * 4] = vv;
            }
        }
        if (tid < 64) s.km[tid] = mask[b * N_ + kb + tid];
        __syncthreads();

        // S = Q @ K^T
        float acc[4][4] = {};
        #pragma unroll 8
        for (int e = 0; e < 128; e++) {
            float a0 = s.Qs[e][ty * 4 + 0];
            float a1 = s.Qs[e][ty * 4 + 1];
            float a2 = s.Qs[e][ty * 4 + 2];
            float a3 = s.Qs[e][ty * 4 + 3];
            float b0 = s.Ks[e][tx * 4 + 0];
            float b1 = s.Ks[e][tx * 4 + 1];
            float b2 = s.Ks[e][tx * 4 + 2];
            float b3 = s.Ks[e][tx * 4 + 3];
            acc[0][0] += a0 * b0; acc[0][1] += a0 * b1; acc[0][2] += a0 * b2; acc[0][3] += a0 * b3;
            acc[1][0] += a1 * b0; acc[1][1] += a1 * b1; acc[1][2] += a1 * b2; acc[1][3] += a1 * b3;
            acc[2][0] += a2 * b0; acc[2][1] += a2 * b1; acc[2][2] += a2 * b2; acc[2][3] += a2 * b3;
            acc[3][0] += a3 * b0; acc[3][1] += a3 * b1; acc[3][2] += a3 * b2; acc[3][3] += a3 * b3;
        }
        // scale + mask -> Ps
        #pragma unroll
        for (int i = 0; i < 4; i++) {
            int r = ty * 4 + i;
            #pragma unroll
            for (int j = 0; j < 4; j++) {
                int c = tx * 4 + j;
                float v = (s.qm[r] && s.km[c]) ? acc[i][j] * SCALE_ : NEG_;
                s.Ps[r][c] = v;
            }
        }
        __syncthreads();

        // online softmax per row (threads 0..63 own one row each)
        if (tid < 64) {
            const int r = tid;
            float m = s.row_max[r];
            float cm = -3.0e38f;
            #pragma unroll 8
            for (int c = 0; c < 64; c++) cm = fmaxf(cm, s.Ps[r][c]);
            float nm = fmaxf(m, cm);
            float al = __expf(m - nm);
            float sum = 0.0f;
            #pragma unroll 8
            for (int c = 0; c < 64; c++) {
                float p = __expf(s.Ps[r][c] - nm);
                s.Ps[r][c] = p;
                sum += p;
            }
            s.row_sum[r] = s.row_sum[r] * al + sum;
            s.row_max[r] = nm;
            s.alpha[r]   = al;
        }
        __syncthreads();

        // rescale O, then O += P @ V
        float al[4];
        #pragma unroll
        for (int i = 0; i < 4; i++) {
            al[i] = s.alpha[ty * 4 + i];
            #pragma unroll
            for (int j = 0; j < 8; j++) o[i][j] *= al[i];
        }
        #pragma unroll 4
        for (int kk = 0; kk < 64; kk++) {
            float p0 = s.Ps[ty * 4 + 0][kk];
            float p1 = s.Ps[ty * 4 + 1][kk];
            float p2 = s.Ps[ty * 4 + 2][kk];
            float p3 = s.Ps[ty * 4 + 3][kk];
            float4 v0 = *(const float4*)&s.Vs[kk][tx * 8];
            float4 v1 = *(const float4*)&s.Vs[kk][tx * 8 + 4];
            float vv[8] = {v0.x, v0.y, v0.z, v0.w, v1.x, v1.y, v1.z, v1.w};
            #pragma unroll
            for (int j = 0; j < 8; j++) {
                o[0][j] += p0 * vv[j];
                o[1][j] += p1 * vv[j];
                o[2][j] += p2 * vv[j];
                o[3][j] += p3 * vv[j];
            }
        }
    }

    // epilogue: divide by denominator, write concatenated [b][n][h*128+e]
    #pragma unroll
    for (int i = 0; i < 4; i++) {
        int r = rowBase + ty * 4 + i;
        float inv = 1.0f / s.row_sum[ty * 4 + i];
        float* dst = g_att + ((size_t)b * N_ + r) * D_ + h * HD_ + tx * 8;
        float4 w0, w1;
        w0.x = o[i][0] * inv; w0.y = o[i][1] * inv; w0.z = o[i][2] * inv; w0.w = o[i][3] * inv;
        w1.x = o[i][4] * inv; w1.y = o[i][5] * inv; w1.z = o[i][6] * inv; w1.w = o[i][7] * inv;
        *(float4*)dst = w0;
        *(float4*)(dst + 4) = w1;
    }
}

// ============================================================================
// Kernel 3: final FC.  out[b] = g_att[b] @ Wfc + bfc
// ============================================================================
__global__ __launch_bounds__(256) void fc_kernel(
    const float* __restrict__ Wfc, const float* __restrict__ bfc,
    float* __restrict__ out)
{
    __shared__ float As[16][64];
    __shared__ float Bs[16][64];

    const int b = blockIdx.z;
    const int rowBase = blockIdx.y * 64;
    const int colBase = blockIdx.x * 64;

    const float* A = g_att + (size_t)b * N_ * D_;

    const int tid = threadIdx.x;
    const int tx = tid & 15, ty = tid >> 4;

    float c[4][4] = {};

    const int ar  = tid >> 2;
    const int ak  = (tid & 3) * 4;
    const int wc  = tid & 63;
    const int wk0 = tid >> 6;

    for (int k0 = 0; k0 < D_; k0 += 16) {
        float4 av = *(const float4*)(A + (size_t)(rowBase + ar) * D_ + k0 + ak);
        As[ak + 0][ar] = av.x;
        As[ak + 1][ar] = av.y;
        As[ak + 2][ar] = av.z;
        As[ak + 3][ar] = av.w;
        #pragma unroll
        for (int i = 0; i < 4; i++) {
            int kk = wk0 + i * 4;
            Bs[kk][wc] = Wfc[(size_t)(k0 + kk) * D_ + colBase + wc];
        }
        __syncthreads();
        #pragma unroll
        for (int kk = 0; kk < 16; kk++) {
            float4 a4 = *(const float4*)&As[kk][ty * 4];
            float4 b4 = *(const float4*)&Bs[kk][tx * 4];
            float a[4] = {a4.x, a4.y, a4.z, a4.w};
            float bb[4] = {b4.x, b4.y, b4.z, b4.w};
            #pragma unroll
            for (int i = 0; i < 4; i++)
                #pragma unroll
                for (int j = 0; j < 4; j++)
                    c[i][j] += a[i] * bb[j];
        }
        __syncthreads();
    }

    #pragma unroll
    for (int i = 0; i < 4; i++) {
        int row = rowBase + ty * 4 + i;
        float* dst = out + ((size_t)b * N_ + row) * D_ + colBase + tx * 4;
        #pragma unroll
        for (int j = 0; j < 4; j++)
            dst[j] = c[i][j] + bfc[colBase + tx * 4 + j];
    }
}

// ============================================================================
extern "C" void kernel_launch(void* const* d_in, const int* in_sizes, int n_in,
                              void* d_out, int out_size)
{
    const float* x    = (const float*)d_in[0];
    const int*   xm   = (const int*)d_in[1];
    const float* Wq   = (const float*)d_in[2];
    const float* bq   = (const float*)d_in[3];
    const float* Wk   = (const float*)d_in[4];
    const float* bk   = (const float*)d_in[5];
    const float* Wv   = (const float*)d_in[6];
    const float* bv   = (const float*)d_in[7];
    const float* Wfc  = (const float*)d_in[8];
    const float* bfc  = (const float*)d_in[9];
    float* out = (float*)d_out;

    cudaFuncSetAttribute(attn_kernel,
                         cudaFuncAttributeMaxDynamicSharedMemorySize,
                         (int)sizeof(AttnSmem));

    dim3 qkvGrid(HD_ / 64, N_ / 64, B_ * H_);
    qkv_kernel<<<qkvGrid, 256>>>(x, Wq, bq, Wk, bk, Wv, bv);

    dim3 attnGrid(N_ / 64, B_ * H_);
    attn_kernel<<<attnGrid, 256, sizeof(AttnSmem)>>>(xm);

    dim3 fcGrid(D_ / 64, N_ / 64, B_);
    fc_kernel<<<fcGrid, 256>>>(Wfc, bfc, out);
}

// round 2
// speedup vs baseline: 2.5705x; 2.5705x over previous
#include <cuda_runtime.h>
#include <math.h>

#define B_   16
#define N_   1024
#define D_   1024
#define H_   8
#define HD_  128
#define M_TOT (B_*N_)              /* 16384 */
#define SCALE_ 0.08838834764831845f /* 1/sqrt(128) */
#define NEG_   (-1.0e30f)

// -------- scratch (device globals; allocation is forbidden) --------
__device__ float g_q[(size_t)M_TOT * D_];   // [b*N+n][h*128+e]
__device__ float g_k[(size_t)M_TOT * D_];
__device__ float g_v[(size_t)M_TOT * D_];
__device__ float g_att[(size_t)M_TOT * D_];

// -------- tf32 helpers --------
__device__ __forceinline__ unsigned f2tf(float x) {
    unsigned r; asm("cvt.rna.tf32.f32 %0, %1;" : "=r"(r) : "f"(x)); return r;
}
__device__ __forceinline__ void mma_tf32(float* d, const unsigned* a, const unsigned* b) {
    asm volatile("mma.sync.aligned.m16n8k8.row.col.f32.tf32.tf32.f32 "
        "{%0,%1,%2,%3},{%4,%5,%6,%7},{%8,%9},{%0,%1,%2,%3};"
        : "+f"(d[0]), "+f"(d[1]), "+f"(d[2]), "+f"(d[3])
        : "r"(a[0]), "r"(a[1]), "r"(a[2]), "r"(a[3]), "r"(b[0]), "r"(b[1]));
}

// ============================================================================
// Generic tf32 GEMM:  C[16384 x 1024] = A[16384 x 1024] @ B + bias
// headMode=1: B = per-head weights [H][1024][128], col-tile == head
// headMode=0: B = flat [1024][1024]
// Block tile 128x128, BK=16, 256 threads (8 warps, 4x2), warp tile 32x64.
// ============================================================================
__global__ void __launch_bounds__(256, 2) gemm_tf32_kernel(
    const float* __restrict__ A,
    const float* __restrict__ Bsrc,
    const float* __restrict__ bias,
    float* __restrict__ C,
    int headMode)
{
    __shared__ unsigned As[128][20];   // stride 20 -> conflict-free A frags
    __shared__ unsigned Bs[16][136];   // stride 136 -> conflict-free B frags

    const int rowBase = blockIdx.y * 128;
    const int colTile = blockIdx.x;          // 0..7
    const int colBase = colTile * 128;

    const float* Bp;
    int ldb;
    if (headMode) { Bp = Bsrc + (size_t)colTile * D_ * HD_; ldb = HD_; }
    else          { Bp = Bsrc + colBase;                    ldb = D_;  }

    const int tid  = threadIdx.x;
    const int w    = tid >> 5;
    const int lane = tid & 31;
    const int g    = lane >> 2;
    const int t4   = lane & 3;
    const int warpM = (w & 3) * 32;
    const int warpN = (w >> 2) * 64;

    float c[2][8][4];
    #pragma unroll
    for (int mt = 0; mt < 2; mt++)
        #pragma unroll
        for (int nt = 0; nt < 8; nt++)
            #pragma unroll
            for (int i = 0; i < 4; i++) c[mt][nt][i] = 0.0f;

    const int arow = tid >> 2;          // 0..63  (and +64)
    const int acol = (tid & 3) * 4;
    const int brow = tid >> 4;          // 0..15
    const int bcol = (tid & 15) * 8;

    for (int k0 = 0; k0 < D_; k0 += 16) {
        float4 av0 = *(const float4*)(A + (size_t)(rowBase + arow) * D_ + k0 + acol);
        float4 av1 = *(const float4*)(A + (size_t)(rowBase + arow + 64) * D_ + k0 + acol);
        As[arow][acol + 0] = f2tf(av0.x);
        As[arow][acol + 1] = f2tf(av0.y);
        As[arow][acol + 2] = f2tf(av0.z);
        As[arow][acol + 3] = f2tf(av0.w);
        As[arow + 64][acol + 0] = f2tf(av1.x);
        As[arow + 64][acol + 1] = f2tf(av1.y);
        As[arow + 64][acol + 2] = f2tf(av1.z);
        As[arow + 64][acol + 3] = f2tf(av1.w);

        float4 bv0 = *(const float4*)(Bp + (size_t)(k0 + brow) * ldb + bcol);
        float4 bv1 = *(const float4*)(Bp + (size_t)(k0 + brow) * ldb + bcol + 4);
        Bs[brow][bcol + 0] = f2tf(bv0.x);
        Bs[brow][bcol + 1] = f2tf(bv0.y);
        Bs[brow][bcol + 2] = f2tf(bv0.z);
        Bs[brow][bcol + 3] = f2tf(bv0.w);
        Bs[brow][bcol + 4] = f2tf(bv1.x);
        Bs[brow][bcol + 5] = f2tf(bv1.y);
        Bs[brow][bcol + 6] = f2tf(bv1.z);
        Bs[brow][bcol + 7] = f2tf(bv1.w);
        __syncthreads();

        #pragma unroll
        for (int ks = 0; ks < 2; ks++) {
            const int kk = ks * 8;
            unsigned af[2][4], bf[8][2];
            #pragma unroll
            for (int mt = 0; mt < 2; mt++) {
                int r = warpM + mt * 16 + g;
                af[mt][0] = As[r][kk + t4];
                af[mt][1] = As[r + 8][kk + t4];
                af[mt][2] = As[r][kk + t4 + 4];
                af[mt][3] = As[r + 8][kk + t4 + 4];
            }
            #pragma unroll
            for (int nt = 0; nt < 8; nt++) {
                int cc = warpN + nt * 8 + g;
                bf[nt][0] = Bs[kk + t4][cc];
                bf[nt][1] = Bs[kk + t4 + 4][cc];
            }
            #pragma unroll
            for (int mt = 0; mt < 2; mt++)
                #pragma unroll
                for (int nt = 0; nt < 8; nt++)
                    mma_tf32(c[mt][nt], af[mt], bf[nt]);
        }
        __syncthreads();
    }

    // epilogue
    #pragma unroll
    for (int mt = 0; mt < 2; mt++) {
        int r0 = rowBase + warpM + mt * 16 + g;
        int r1 = r0 + 8;
        #pragma unroll
        for (int nt = 0; nt < 8; nt++) {
            int cc = colBase + warpN + nt * 8 + t4 * 2;
            float bx = bias[cc], by = bias[cc + 1];
            float2 w0 = make_float2(c[mt][nt][0] + bx, c[mt][nt][1] + by);
            float2 w1 = make_float2(c[mt][nt][2] + bx, c[mt][nt][3] + by);
            *(float2*)(C + (size_t)r0 * D_ + cc) = w0;
            *(float2*)(C + (size_t)r1 * D_ + cc) = w1;
        }
    }
}

// ============================================================================
// Flash attention, tf32 mma for QK^T and PV, online softmax, padding mask.
// Block: (b,h) x 64 query rows. 256 threads. 64-key chunks.
// ============================================================================
struct ASmem {
    unsigned Qs[64][132];   // [qrow][e]    tf32 bits
    unsigned Ks[64][132];   // [key][e]
    unsigned Vs[64][136];   // [key][e]
    float    Ps[64][68];    // scores -> probs
    float    row_max[64];
    float    row_sum[64];
    float    alpha[64];
    int      qm[64];
    int      km[64];
};

__global__ void __launch_bounds__(256) attn_kernel(const int* __restrict__ mask)
{
    extern __shared__ char smem_raw[];
    ASmem& s = *reinterpret_cast<ASmem*>(smem_raw);

    const int bh = blockIdx.y;
    const int b  = bh >> 3;
    const int h  = bh & 7;
    const int rowBase = blockIdx.x * 64;

    const int tid  = threadIdx.x;
    const int w    = tid >> 5;
    const int lane = tid & 31;
    const int g    = lane >> 2;
    const int t4   = lane & 3;
    const int warpMs = (w & 3) * 16;       // S-phase rows (also PV rows)
    const int warpNs = (w >> 2) * 32;      // S-phase cols (keys)
    const int warpNp = (w >> 2) * 64;      // PV-phase cols (e)

    const float* Qg = g_q + ((size_t)(b * N_ + rowBase)) * D_ + h * HD_;
    const float* Kg = g_k + ((size_t)(b * N_)) * D_ + h * HD_;
    const float* Vg = g_v + ((size_t)(b * N_)) * D_ + h * HD_;

    const int lrow = tid >> 2;          // 0..63
    const int lcol = (tid & 3) * 4;     // + 16*i

    // load Q tile (tf32-rounded)
    #pragma unroll
    for (int i = 0; i < 8; i++) {
        int cc = lcol + 16 * i;
        float4 v = *(const float4*)(Qg + (size_t)lrow * D_ + cc);
        s.Qs[lrow][cc + 0] = f2tf(v.x);
        s.Qs[lrow][cc + 1] = f2tf(v.y);
        s.Qs[lrow][cc + 2] = f2tf(v.z);
        s.Qs[lrow][cc + 3] = f2tf(v.w);
    }
    if (tid < 64) {
        s.row_max[tid] = -3.0e38f;
        s.row_sum[tid] = 0.0f;
        s.qm[tid] = mask[b * N_ + rowBase + tid];
    }

    float o[8][4];
    #pragma unroll
    for (int nt = 0; nt < 8; nt++)
        #pragma unroll
        for (int i = 0; i < 4; i++) o[nt][i] = 0.0f;

    const int r0 = warpMs + g;
    const int r1 = r0 + 8;

    for (int kb = 0; kb < N_; kb += 64) {
        __syncthreads();   // protect Ks/Vs/km/Ps reuse
        #pragma unroll
        for (int i = 0; i < 8; i++) {
            int cc = lcol + 16 * i;
            float4 kv = *(const float4*)(Kg + (size_t)(kb + lrow) * D_ + cc);
            s.Ks[lrow][cc + 0] = f2tf(kv.x);
            s.Ks[lrow][cc + 1] = f2tf(kv.y);
            s.Ks[lrow][cc + 2] = f2tf(kv.z);
            s.Ks[lrow][cc + 3] = f2tf(kv.w);
            float4 vv = *(const float4*)(Vg + (size_t)(kb + lrow) * D_ + cc);
            s.Vs[lrow][cc + 0] = f2tf(vv.x);
            s.Vs[lrow][cc + 1] = f2tf(vv.y);
            s.Vs[lrow][cc + 2] = f2tf(vv.z);
            s.Vs[lrow][cc + 3] = f2tf(vv.w);
        }
        if (tid < 64) s.km[tid] = mask[b * N_ + kb + tid];
        __syncthreads();

        // ---- S = Q @ K^T (warp: 16 q-rows x 32 keys) ----
        float sf[4][4];
        #pragma unroll
        for (int nt = 0; nt < 4; nt++)
            #pragma unroll
            for (int i = 0; i < 4; i++) sf[nt][i] = 0.0f;

        #pragma unroll
        for (int kk = 0; kk < 128; kk += 8) {
            unsigned af[4];
            af[0] = s.Qs[r0][kk + t4];
            af[1] = s.Qs[r1][kk + t4];
            af[2] = s.Qs[r0][kk + t4 + 4];
            af[3] = s.Qs[r1][kk + t4 + 4];
            #pragma unroll
            for (int nt = 0; nt < 4; nt++) {
                int kcol = warpNs + nt * 8 + g;
                unsigned bf[2];
                bf[0] = s.Ks[kcol][kk + t4];
                bf[1] = s.Ks[kcol][kk + t4 + 4];
                mma_tf32(sf[nt], af, bf);
            }
        }

        // ---- scale + mask -> Ps ----
        const int qm0 = s.qm[r0], qm1 = s.qm[r1];
        #pragma unroll
        for (int nt = 0; nt < 4; nt++) {
            int cb = warpNs + nt * 8 + t4 * 2;
            int k0m = s.km[cb], k1m = s.km[cb + 1];
            s.Ps[r0][cb]     = (qm0 && k0m) ? sf[nt][0] * SCALE_ : NEG_;
            s.Ps[r0][cb + 1] = (qm0 && k1m) ? sf[nt][1] * SCALE_ : NEG_;
            s.Ps[r1][cb]     = (qm1 && k0m) ? sf[nt][2] * SCALE_ : NEG_;
            s.Ps[r1][cb + 1] = (qm1 && k1m) ? sf[nt][3] * SCALE_ : NEG_;
        }
        __syncthreads();

        // ---- online softmax, one thread per row ----
        if (tid < 64) {
            const int r = tid;
            float m = s.row_max[r];
            float cm = -3.0e38f;
            #pragma unroll 8
            for (int c = 0; c < 64; c++) cm = fmaxf(cm, s.Ps[r][c]);
            float nm = fmaxf(m, cm);
            float al = __expf(m - nm);
            float sum = 0.0f;
            #pragma unroll 8
            for (int c = 0; c < 64; c++) {
                float p = __expf(s.Ps[r][c] - nm);
                s.Ps[r][c] = p;
                sum += p;
            }
            s.row_sum[r] = s.row_sum[r] * al + sum;
            s.row_max[r] = nm;
            s.alpha[r]   = al;
        }
        __syncthreads();

        // ---- O = O*alpha + P @ V (warp: 16 rows x 64 e-cols) ----
        float al0 = s.alpha[r0], al1 = s.alpha[r1];
        #pragma unroll
        for (int nt = 0; nt < 8; nt++) {
            o[nt][0] *= al0; o[nt][1] *= al0;
            o[nt][2] *= al1; o[nt][3] *= al1;
        }
        #pragma unroll
        for (int kk = 0; kk < 64; kk += 8) {
            unsigned af[4];
            af[0] = f2tf(s.Ps[r0][kk + t4]);
            af[1] = f2tf(s.Ps[r1][kk + t4]);
            af[2] = f2tf(s.Ps[r0][kk + t4 + 4]);
            af[3] = f2tf(s.Ps[r1][kk + t4 + 4]);
            #pragma unroll
            for (int nt = 0; nt < 8; nt++) {
                int ec = warpNp + nt * 8 + g;
                unsigned bf[2];
                bf[0] = s.Vs[kk + t4][ec];
                bf[1] = s.Vs[kk + t4 + 4][ec];
                mma_tf32(o[nt], af, bf);
            }
        }
    }

    // ---- epilogue: divide by denom, write concatenated head block ----
    float inv0 = 1.0f / s.row_sum[r0];
    float inv1 = 1.0f / s.row_sum[r1];
    size_t gr0 = (size_t)(b * N_ + rowBase + r0) * D_;
    size_t gr1 = (size_t)(b * N_ + rowBase + r1) * D_;
    #pragma unroll
    for (int nt = 0; nt < 8; nt++) {
        int cc = h * HD_ + warpNp + nt * 8 + t4 * 2;
        float2 w0 = make_float2(o[nt][0] * inv0, o[nt][1] * inv0);
        float2 w1 = make_float2(o[nt][2] * inv1, o[nt][3] * inv1);
        *(float2*)(g_att + gr0 + cc) = w0;
        *(float2*)(g_att + gr1 + cc) = w1;
    }
}

// ============================================================================
extern "C" void kernel_launch(void* const* d_in, const int* in_sizes, int n_in,
                              void* d_out, int out_size)
{
    const float* x    = (const float*)d_in[0];
    const int*   xm   = (const int*)d_in[1];
    const float* Wq   = (const float*)d_in[2];
    const float* bq   = (const float*)d_in[3];
    const float* Wk   = (const float*)d_in[4];
    const float* bk   = (const float*)d_in[5];
    const float* Wv   = (const float*)d_in[6];
    const float* bv   = (const float*)d_in[7];
    const float* Wfc  = (const float*)d_in[8];
    const float* bfc  = (const float*)d_in[9];
    float* out = (float*)d_out;

    float *qp, *kp, *vp, *ap;
    cudaGetSymbolAddress((void**)&qp, g_q);
    cudaGetSymbolAddress((void**)&kp, g_k);
    cudaGetSymbolAddress((void**)&vp, g_v);
    cudaGetSymbolAddress((void**)&ap, g_att);

    cudaFuncSetAttribute(attn_kernel,
                         cudaFuncAttributeMaxDynamicSharedMemorySize,
                         (int)sizeof(ASmem));

    dim3 gGrid(8, 128);
    gemm_tf32_kernel<<<gGrid, 256>>>(x, Wq, bq, qp, 1);
    gemm_tf32_kernel<<<gGrid, 256>>>(x, Wk, bk, kp, 1);
    gemm_tf32_kernel<<<gGrid, 256>>>(x, Wv, bv, vp, 1);

    dim3 aGrid(N_ / 64, B_ * H_);
    attn_kernel<<<aGrid, 256, sizeof(ASmem)>>>(xm);

    gemm_tf32_kernel<<<gGrid, 256>>>(ap, Wfc, bfc, out, 0);
}